// round 16
// baseline (speedup 1.0000x reference)
#include <cuda_runtime.h>
#include <math.h>
#include <stdint.h>

#define T_STEPS 512
#define BATCH   64
#define IN_DIM  1024
#define HID     1024
#define BH      (BATCH * HID)          // 65536

// ---------- helpers ----------
__device__ __forceinline__ uint32_t f2tf32(float f) {
    uint32_t r;
    asm("cvt.rna.tf32.f32 %0, %1;" : "=r"(r) : "f"(f));
    return r;
}

__device__ __forceinline__ float tanh_fast(float x) {
    float y;
    asm("tanh.approx.f32 %0, %1;" : "=f"(y) : "f"(x));
    return y;
}

__device__ __forceinline__ void mma_tf32(float c[4], const uint32_t a[4], const uint32_t b[2]) {
    asm("mma.sync.aligned.m16n8k8.row.col.f32.tf32.tf32.f32 "
        "{%0,%1,%2,%3}, {%4,%5,%6,%7}, {%8,%9}, {%0,%1,%2,%3};\n"
        : "+f"(c[0]), "+f"(c[1]), "+f"(c[2]), "+f"(c[3])
        : "r"(a[0]), "r"(a[1]), "r"(a[2]), "r"(a[3]), "r"(b[0]), "r"(b[1]));
}

__device__ __forceinline__ unsigned ld_relaxed(const unsigned* p) {
    unsigned v;
    asm volatile("ld.relaxed.gpu.global.u32 %0, [%1];" : "=r"(v) : "l"(p) : "memory");
    return v;
}

__device__ __forceinline__ void red_release(unsigned* p) {
    asm volatile("red.release.gpu.global.add.u32 [%0], %1;" :: "l"(p), "r"(1u) : "memory");
}

__device__ __forceinline__ uint32_t smem_u32(const void* p) {
    return (uint32_t)__cvta_generic_to_shared(p);
}

__device__ __forceinline__ void cp_async16(uint32_t dst, const void* src) {
    asm volatile("cp.async.ca.shared.global [%0], [%1], 16;\n" :: "r"(dst), "l"(src));
}

__device__ __forceinline__ void cp_commit() {
    asm volatile("cp.async.commit_group;\n" ::);
}

template <int N>
__device__ __forceinline__ void cp_wait() {
    asm volatile("cp.async.wait_group %0;\n" :: "n"(N));
}

// ============================================================
// Kernel 1: Xp = X @ W_xh + b — 3-stage cp.async, BK=32,
// 512 threads = 16 warps (4m x 4n), warp tile 32m x 32n.
// 4 warps/SMSP for latency hiding (fix for 2-warp/SMSP stall).
// ============================================================
#define XP_AS 36    // 32 + 4 words; row stride 144 B (16B multiple)
#define XP_BS 136   // 128 + 8 words; row stride 544 B (16B multiple)
#define XP_A_WORDS (128 * XP_AS)                 // 4608
#define XP_B_WORDS (32 * XP_BS)                  // 4352
#define XP_STAGE_WORDS (XP_A_WORDS + XP_B_WORDS) // 8960
#define XP_SMEM_BYTES (3 * XP_STAGE_WORDS * 4)   // 107520

__global__ __launch_bounds__(512) void xp_gemm_tf32(const float* __restrict__ A,
                                                    const float* __restrict__ B,
                                                    const float* __restrict__ bias,
                                                    float* __restrict__ C) {
    extern __shared__ __align__(16) float xsm[];
    __shared__ float biasS[128];

    const int bm  = blockIdx.y * 128;
    const int bn  = blockIdx.x * 128;
    const int tid = threadIdx.x;
    const int wid = tid >> 5;          // 0..15
    const int lane = tid & 31;
    const int gr  = lane >> 2;
    const int tg  = lane & 3;
    const int m_warp = wid & 3;        // 0..3 -> 32 rows each
    const int n_warp = wid >> 2;       // 0..3 -> 32 cols each

    if (tid < 128) biasS[tid] = bias[bn + tid];

    auto As = [&](int s, int row, int k) -> float* {
        return &xsm[s * XP_STAGE_WORDS + row * XP_AS + k];
    };
    auto Bs = [&](int s, int kk, int n) -> float* {
        return &xsm[s * XP_STAGE_WORDS + XP_A_WORDS + kk * XP_BS + n];
    };

    auto load_chunk = [&](int c, int buf) {
        const int k0 = c * 32;
        // A chunk: 128 x 32 = 1024 float4 / 512 thr = 2 each
        #pragma unroll
        for (int j = 0; j < 2; j++) {
            int idx = tid + j * 512;         // 0..1023
            int row = idx >> 3;              // 0..127
            int kq  = (idx & 7) * 4;         // 0..28
            cp_async16(smem_u32(As(buf, row, kq)),
                       &A[(size_t)(bm + row) * IN_DIM + k0 + kq]);
        }
        // B chunk: 32 x 128 = 1024 float4 / 512 thr = 2 each
        #pragma unroll
        for (int j = 0; j < 2; j++) {
            int idx = tid + j * 512;         // 0..1023
            int kk  = idx >> 5;              // 0..31
            int nq  = (idx & 31) * 4;        // 0..124
            cp_async16(smem_u32(Bs(buf, kk, nq)),
                       &B[(size_t)(k0 + kk) * HID + bn + nq]);
        }
    };

    float acc[2][4][4] = {};   // [m16][n8][frag] — 32 regs

    load_chunk(0, 0); cp_commit();
    load_chunk(1, 1); cp_commit();
    load_chunk(2, 2); cp_commit();

    const int NCHUNK = IN_DIM / 32;   // 32
    for (int c = 0; c < NCHUNK; c++) {
        const int buf = c % 3;
        cp_wait<2>();               // chunk c resident
        __syncthreads();

        #pragma unroll
        for (int k8i = 0; k8i < 4; k8i++) {
            const int k8 = k8i * 8;
            uint32_t bf[4][2];
            #pragma unroll
            for (int nt = 0; nt < 4; nt++) {
                int nn = n_warp * 32 + nt * 8 + gr;
                bf[nt][0] = f2tf32(*Bs(buf, k8 + tg, nn));
                bf[nt][1] = f2tf32(*Bs(buf, k8 + tg + 4, nn));
            }
            #pragma unroll
            for (int mt = 0; mt < 2; mt++) {
                int mb = m_warp * 32 + mt * 16;
                uint32_t af[4];
                af[0] = f2tf32(*As(buf, mb + gr, k8 + tg));
                af[1] = f2tf32(*As(buf, mb + gr + 8, k8 + tg));
                af[2] = f2tf32(*As(buf, mb + gr, k8 + tg + 4));
                af[3] = f2tf32(*As(buf, mb + gr + 8, k8 + tg + 4));
                #pragma unroll
                for (int nt = 0; nt < 4; nt++)
                    mma_tf32(acc[mt][nt], af, bf[nt]);
            }
        }
        __syncthreads();            // everyone done reading buf

        if (c + 3 < NCHUNK) load_chunk(c + 3, (c + 3) % 3);
        cp_commit();
    }

    #pragma unroll
    for (int mt = 0; mt < 2; mt++) {
        #pragma unroll
        for (int nt = 0; nt < 4; nt++) {
            int colL = n_warp * 32 + nt * 8 + 2 * tg;
            int row0 = bm + m_warp * 32 + mt * 16 + gr;
            float2 v0, v1;
            v0.x = acc[mt][nt][0] + biasS[colL];
            v0.y = acc[mt][nt][1] + biasS[colL + 1];
            v1.x = acc[mt][nt][2] + biasS[colL];
            v1.y = acc[mt][nt][3] + biasS[colL + 1];
            *reinterpret_cast<float2*>(&C[(size_t)row0 * HID + bn + colL]) = v0;
            *reinterpret_cast<float2*>(&C[(size_t)(row0 + 8) * HID + bn + colL]) = v1;
        }
    }
}

// ============================================================
// Persistent scan v4 — fused-reduce split-K, ONE global round/step.
// (Byte-identical to round 11/12 — validated WIN.)
// ============================================================
#define SC_BLOCKS 128
#define HS_STRIDE 144
#define FSTRIDE   32

__device__ float    g_part[2 * 8 * BH];    // 4 MB, parity-buffered partials
__device__ unsigned g_flag[SC_BLOCKS * FSTRIDE];
__device__ unsigned g_done = 0;

__global__ __launch_bounds__(512, 1) void rnn_scan(const float* __restrict__ W,
                                                   float* __restrict__ out) {
    __shared__ uint32_t hs[16][HS_STRIDE];

    const int tid  = threadIdx.x;
    const int bid  = blockIdx.x;
    const int ks   = bid >> 4;
    const int nb   = (bid >> 2) & 3;
    const int rh   = bid & 3;
    const int wid  = tid >> 5;
    const int lane = tid & 31;
    const int gr   = lane >> 2;
    const int tg   = lane & 3;

    uint32_t bfr[8][2][2][2];
    {
        const int ncol = 256 * nb + 16 * wid;
        #pragma unroll
        for (int u = 0; u < 8; u++)
            #pragma unroll
            for (int p = 0; p < 2; p++)
                #pragma unroll
                for (int nt = 0; nt < 2; nt++) {
                    int n  = ncol + 8 * nt + gr;
                    int kk = 128 * ks + 16 * u + 4 * tg + 2 * p;
                    bfr[u][p][nt][0] = f2tf32(W[(size_t)kk * HID + n]);
                    bfr[u][p][nt][1] = f2tf32(W[(size_t)(kk + 1) * HID + n]);
                }
    }

    const int r   = tid >> 5;
    const int c4  = (tid & 31) * 4;
    const int g_row = 16 * rh + r;
    const size_t my_off = (size_t)g_row * HID + 128 * ks + c4;
    const bool owned = ((r >> 2) == nb);
    float4 saved;

    for (int t = 0; t < T_STEPS; t++) {
        float* o = out + (size_t)t * BH;

        if (t > 0) {
            if (wid < 4) {
                const unsigned* a = &g_flag[(wid * 32 + lane) * FSTRIDE];
                int spins = 0;
                bool done = false;
                while (true) {
                    if (!done) done = (ld_relaxed(a) >= (unsigned)t);
                    if (__ballot_sync(0xffffffffu, !done) == 0) break;
                    if (++spins > 8192) __nanosleep(64);
                }
                asm volatile("fence.acq_rel.gpu;" ::: "memory");
            }
            __syncthreads();

            if (owned)
                *reinterpret_cast<float4*>(&out[(size_t)(t - 1) * BH + my_off]) = saved;
        }

        {
            float4 s = *reinterpret_cast<const float4*>(&o[my_off]);
            if (t > 0) {
                const float* pb = g_part + (size_t)(t & 1) * (8 * BH);
                #pragma unroll
                for (int kk = 0; kk < 8; kk++) {
                    float4 p = *reinterpret_cast<const float4*>(
                        &pb[(size_t)kk * BH + my_off]);
                    s.x += p.x; s.y += p.y; s.z += p.z; s.w += p.w;
                }
            }
            s.x = tanh_fast(s.x); s.y = tanh_fast(s.y);
            s.z = tanh_fast(s.z); s.w = tanh_fast(s.w);
            if (owned) saved = s;
            uint4 w = make_uint4(f2tf32(s.x), f2tf32(s.y), f2tf32(s.z), f2tf32(s.w));
            *reinterpret_cast<uint4*>(&hs[r][c4]) = w;
        }
        __syncthreads();

        if (t < T_STEPS - 1) {
            float acc[2][4] = {};
            #pragma unroll
            for (int u = 0; u < 8; u++) {
                const int kc = 16 * u + 4 * tg;
                uint4 va = *reinterpret_cast<const uint4*>(&hs[gr][kc]);
                uint4 vb = *reinterpret_cast<const uint4*>(&hs[gr + 8][kc]);
                uint32_t afA[4] = {va.x, vb.x, va.y, vb.y};
                uint32_t afB[4] = {va.z, vb.z, va.w, vb.w};
                mma_tf32(acc[0], afA, bfr[u][0][0]);
                mma_tf32(acc[1], afA, bfr[u][0][1]);
                mma_tf32(acc[0], afB, bfr[u][1][0]);
                mma_tf32(acc[1], afB, bfr[u][1][1]);
            }
            float* gp = g_part + (size_t)((t + 1) & 1) * (8 * BH) + (size_t)ks * BH;
            const int ncol = 256 * nb + 16 * wid;
            #pragma unroll
            for (int nt = 0; nt < 2; nt++) {
                int col  = ncol + 8 * nt + 2 * tg;
                int row0 = 16 * rh + gr;
                *reinterpret_cast<float2*>(&gp[(size_t)row0 * HID + col]) =
                    make_float2(acc[nt][0], acc[nt][1]);
                *reinterpret_cast<float2*>(&gp[(size_t)(row0 + 8) * HID + col]) =
                    make_float2(acc[nt][2], acc[nt][3]);
            }
        }
        __syncthreads();
        if (tid == 0) red_release(&g_flag[bid * FSTRIDE]);
    }

    if (wid < 4) {
        const unsigned* a = &g_flag[(wid * 32 + lane) * FSTRIDE];
        int spins = 0;
        bool done = false;
        while (true) {
            if (!done) done = (ld_relaxed(a) >= (unsigned)T_STEPS);
            if (__ballot_sync(0xffffffffu, !done) == 0) break;
            if (++spins > 8192) __nanosleep(64);
        }
        asm volatile("fence.acq_rel.gpu;" ::: "memory");
    }
    __syncthreads();
    if (owned) {
        *reinterpret_cast<float4*>(&out[(size_t)(T_STEPS - 1) * BH + my_off]) = saved;
        *reinterpret_cast<float4*>(&out[(size_t)T_STEPS * BH + my_off]) = saved;
    }

    __syncthreads();
    if (tid == 0) {
        unsigned d = atomicAdd(&g_done, 1u);
        if (d == (unsigned)(gridDim.x - 1)) {
            for (int i = 0; i < SC_BLOCKS; i++) g_flag[i * FSTRIDE] = 0;
            g_done = 0;
            __threadfence();
        }
    }
}

// ============================================================
extern "C" void kernel_launch(void* const* d_in, const int* in_sizes, int n_in,
                              void* d_out, int out_size) {
    const float* X    = (const float*)d_in[0];
    const float* W_xh = (const float*)d_in[1];
    const float* W_hh = (const float*)d_in[2];
    const float* b_h  = (const float*)d_in[3];
    float* out = (float*)d_out;

    {
        cudaFuncSetAttribute(xp_gemm_tf32,
                             cudaFuncAttributeMaxDynamicSharedMemorySize,
                             XP_SMEM_BYTES);
        dim3 grid(HID / 128, (T_STEPS * BATCH) / 128);
        xp_gemm_tf32<<<grid, 512, XP_SMEM_BYTES>>>(X, W_xh, b_h, out);
    }
    rnn_scan<<<SC_BLOCKS, 512>>>(W_hh, out);
}

// round 17
// speedup vs baseline: 1.0502x; 1.0502x over previous
#include <cuda_runtime.h>
#include <math.h>
#include <stdint.h>

#define T_STEPS 512
#define BATCH   64
#define IN_DIM  1024
#define HID     1024
#define BH      (BATCH * HID)          // 65536

// ---------- helpers ----------
__device__ __forceinline__ uint32_t f2tf32(float f) {
    uint32_t r;
    asm("cvt.rna.tf32.f32 %0, %1;" : "=r"(r) : "f"(f));
    return r;
}

__device__ __forceinline__ float tanh_fast(float x) {
    float y;
    asm("tanh.approx.f32 %0, %1;" : "=f"(y) : "f"(x));
    return y;
}

__device__ __forceinline__ void mma_tf32(float c[4], const uint32_t a[4], const uint32_t b[2]) {
    asm("mma.sync.aligned.m16n8k8.row.col.f32.tf32.tf32.f32 "
        "{%0,%1,%2,%3}, {%4,%5,%6,%7}, {%8,%9}, {%0,%1,%2,%3};\n"
        : "+f"(c[0]), "+f"(c[1]), "+f"(c[2]), "+f"(c[3])
        : "r"(a[0]), "r"(a[1]), "r"(a[2]), "r"(a[3]), "r"(b[0]), "r"(b[1]));
}

__device__ __forceinline__ unsigned ld_relaxed(const unsigned* p) {
    unsigned v;
    asm volatile("ld.relaxed.gpu.global.u32 %0, [%1];" : "=r"(v) : "l"(p) : "memory");
    return v;
}

__device__ __forceinline__ void red_release(unsigned* p) {
    asm volatile("red.release.gpu.global.add.u32 [%0], %1;" :: "l"(p), "r"(1u) : "memory");
}

__device__ __forceinline__ uint32_t smem_u32(const void* p) {
    return (uint32_t)__cvta_generic_to_shared(p);
}

__device__ __forceinline__ void cp_async16(uint32_t dst, const void* src) {
    asm volatile("cp.async.ca.shared.global [%0], [%1], 16;\n" :: "r"(dst), "l"(src));
}

__device__ __forceinline__ void cp_commit() {
    asm volatile("cp.async.commit_group;\n" ::);
}

template <int N>
__device__ __forceinline__ void cp_wait() {
    asm volatile("cp.async.wait_group %0;\n" :: "n"(N));
}

// ============================================================
// Kernel 1: Xp = X @ W_xh + b — R12 structure (best measured) +
// __launch_bounds__(256, 2): 2 blocks/SM for wave overlap.
// Block 128m x 128n, BK=16, 2-stage cp.async, 8 warps (4m x 2n),
// warp tile 32m x 64n. cvt.rna at fragment read (numerics identical).
// ============================================================
#define XP_AS 20    // 16 + 4 pad (words); row stride 80 B (16B multiple)
#define XP_BS 136   // 128 + 8 pad (words); row stride 544 B (16B multiple)

__global__ __launch_bounds__(256, 2) void xp_gemm_tf32(const float* __restrict__ A,
                                                       const float* __restrict__ B,
                                                       const float* __restrict__ bias,
                                                       float* __restrict__ C) {
    __shared__ __align__(16) float As[2][128][XP_AS];
    __shared__ __align__(16) float Bs[2][16][XP_BS];
    __shared__ float biasS[128];

    const int bm  = blockIdx.y * 128;
    const int bn  = blockIdx.x * 128;
    const int tid = threadIdx.x;
    const int wid = tid >> 5;
    const int lane = tid & 31;
    const int gr  = lane >> 2;
    const int tg  = lane & 3;
    const int m_warp = wid & 3;        // 0..3 -> 32 rows each
    const int n_warp = wid >> 2;       // 0..1 -> 64 cols each

    if (tid < 128) biasS[tid] = bias[bn + tid];

    auto load_chunk = [&](int c, int buf) {
        const int k0 = c * 16;
        #pragma unroll
        for (int j = 0; j < 2; j++) {
            int idx = tid + j * 256;         // 0..511
            int row = idx >> 2;              // 0..127
            int kq  = (idx & 3) * 4;         // 0,4,8,12
            cp_async16(smem_u32(&As[buf][row][kq]),
                       &A[(size_t)(bm + row) * IN_DIM + k0 + kq]);
        }
        #pragma unroll
        for (int j = 0; j < 2; j++) {
            int idx = tid + j * 256;         // 0..511
            int kk  = idx >> 5;              // 0..15
            int nq  = (idx & 31) * 4;        // 0..124
            cp_async16(smem_u32(&Bs[buf][kk][nq]),
                       &B[(size_t)(k0 + kk) * HID + bn + nq]);
        }
        cp_commit();
    };

    float acc[2][8][4] = {};   // [m16][n8][frag]

    load_chunk(0, 0);

    for (int c = 0; c < IN_DIM / 16; c++) {
        const int buf = c & 1;
        if (c < IN_DIM / 16 - 1) {
            load_chunk(c + 1, (c + 1) & 1);
            cp_wait<1>();
        } else {
            cp_wait<0>();
        }
        __syncthreads();

        #pragma unroll
        for (int k8i = 0; k8i < 2; k8i++) {
            const int k8 = k8i * 8;
            uint32_t bf[8][2];
            #pragma unroll
            for (int nt = 0; nt < 8; nt++) {
                int nn = n_warp * 64 + nt * 8 + gr;
                bf[nt][0] = f2tf32(Bs[buf][k8 + tg][nn]);
                bf[nt][1] = f2tf32(Bs[buf][k8 + tg + 4][nn]);
            }
            #pragma unroll
            for (int mt = 0; mt < 2; mt++) {
                int mb = m_warp * 32 + mt * 16;
                uint32_t af[4];
                af[0] = f2tf32(As[buf][mb + gr][k8 + tg]);
                af[1] = f2tf32(As[buf][mb + gr + 8][k8 + tg]);
                af[2] = f2tf32(As[buf][mb + gr][k8 + tg + 4]);
                af[3] = f2tf32(As[buf][mb + gr + 8][k8 + tg + 4]);
                #pragma unroll
                for (int nt = 0; nt < 8; nt++)
                    mma_tf32(acc[mt][nt], af, bf[nt]);
            }
        }
        __syncthreads();
    }

    #pragma unroll
    for (int mt = 0; mt < 2; mt++) {
        #pragma unroll
        for (int nt = 0; nt < 8; nt++) {
            int colL = n_warp * 64 + nt * 8 + 2 * tg;
            int row0 = bm + m_warp * 32 + mt * 16 + gr;
            float2 v0, v1;
            v0.x = acc[mt][nt][0] + biasS[colL];
            v0.y = acc[mt][nt][1] + biasS[colL + 1];
            v1.x = acc[mt][nt][2] + biasS[colL];
            v1.y = acc[mt][nt][3] + biasS[colL + 1];
            *reinterpret_cast<float2*>(&C[(size_t)row0 * HID + bn + colL]) = v0;
            *reinterpret_cast<float2*>(&C[(size_t)(row0 + 8) * HID + bn + colL]) = v1;
        }
    }
}

// ============================================================
// Persistent scan v4 — fused-reduce split-K, ONE global round/step.
// (Byte-identical to rounds 11-16 — validated.)
// ============================================================
#define SC_BLOCKS 128
#define HS_STRIDE 144
#define FSTRIDE   32

__device__ float    g_part[2 * 8 * BH];    // 4 MB, parity-buffered partials
__device__ unsigned g_flag[SC_BLOCKS * FSTRIDE];
__device__ unsigned g_done = 0;

__global__ __launch_bounds__(512, 1) void rnn_scan(const float* __restrict__ W,
                                                   float* __restrict__ out) {
    __shared__ uint32_t hs[16][HS_STRIDE];

    const int tid  = threadIdx.x;
    const int bid  = blockIdx.x;
    const int ks   = bid >> 4;
    const int nb   = (bid >> 2) & 3;
    const int rh   = bid & 3;
    const int wid  = tid >> 5;
    const int lane = tid & 31;
    const int gr   = lane >> 2;
    const int tg   = lane & 3;

    uint32_t bfr[8][2][2][2];
    {
        const int ncol = 256 * nb + 16 * wid;
        #pragma unroll
        for (int u = 0; u < 8; u++)
            #pragma unroll
            for (int p = 0; p < 2; p++)
                #pragma unroll
                for (int nt = 0; nt < 2; nt++) {
                    int n  = ncol + 8 * nt + gr;
                    int kk = 128 * ks + 16 * u + 4 * tg + 2 * p;
                    bfr[u][p][nt][0] = f2tf32(W[(size_t)kk * HID + n]);
                    bfr[u][p][nt][1] = f2tf32(W[(size_t)(kk + 1) * HID + n]);
                }
    }

    const int r   = tid >> 5;
    const int c4  = (tid & 31) * 4;
    const int g_row = 16 * rh + r;
    const size_t my_off = (size_t)g_row * HID + 128 * ks + c4;
    const bool owned = ((r >> 2) == nb);
    float4 saved;

    for (int t = 0; t < T_STEPS; t++) {
        float* o = out + (size_t)t * BH;

        if (t > 0) {
            if (wid < 4) {
                const unsigned* a = &g_flag[(wid * 32 + lane) * FSTRIDE];
                int spins = 0;
                bool done = false;
                while (true) {
                    if (!done) done = (ld_relaxed(a) >= (unsigned)t);
                    if (__ballot_sync(0xffffffffu, !done) == 0) break;
                    if (++spins > 8192) __nanosleep(64);
                }
                asm volatile("fence.acq_rel.gpu;" ::: "memory");
            }
            __syncthreads();

            if (owned)
                *reinterpret_cast<float4*>(&out[(size_t)(t - 1) * BH + my_off]) = saved;
        }

        {
            float4 s = *reinterpret_cast<const float4*>(&o[my_off]);
            if (t > 0) {
                const float* pb = g_part + (size_t)(t & 1) * (8 * BH);
                #pragma unroll
                for (int kk = 0; kk < 8; kk++) {
                    float4 p = *reinterpret_cast<const float4*>(
                        &pb[(size_t)kk * BH + my_off]);
                    s.x += p.x; s.y += p.y; s.z += p.z; s.w += p.w;
                }
            }
            s.x = tanh_fast(s.x); s.y = tanh_fast(s.y);
            s.z = tanh_fast(s.z); s.w = tanh_fast(s.w);
            if (owned) saved = s;
            uint4 w = make_uint4(f2tf32(s.x), f2tf32(s.y), f2tf32(s.z), f2tf32(s.w));
            *reinterpret_cast<uint4*>(&hs[r][c4]) = w;
        }
        __syncthreads();

        if (t < T_STEPS - 1) {
            float acc[2][4] = {};
            #pragma unroll
            for (int u = 0; u < 8; u++) {
                const int kc = 16 * u + 4 * tg;
                uint4 va = *reinterpret_cast<const uint4*>(&hs[gr][kc]);
                uint4 vb = *reinterpret_cast<const uint4*>(&hs[gr + 8][kc]);
                uint32_t afA[4] = {va.x, vb.x, va.y, vb.y};
                uint32_t afB[4] = {va.z, vb.z, va.w, vb.w};
                mma_tf32(acc[0], afA, bfr[u][0][0]);
                mma_tf32(acc[1], afA, bfr[u][0][1]);
                mma_tf32(acc[0], afB, bfr[u][1][0]);
                mma_tf32(acc[1], afB, bfr[u][1][1]);
            }
            float* gp = g_part + (size_t)((t + 1) & 1) * (8 * BH) + (size_t)ks * BH;
            const int ncol = 256 * nb + 16 * wid;
            #pragma unroll
            for (int nt = 0; nt < 2; nt++) {
                int col  = ncol + 8 * nt + 2 * tg;
                int row0 = 16 * rh + gr;
                *reinterpret_cast<float2*>(&gp[(size_t)row0 * HID + col]) =
                    make_float2(acc[nt][0], acc[nt][1]);
                *reinterpret_cast<float2*>(&gp[(size_t)(row0 + 8) * HID + col]) =
                    make_float2(acc[nt][2], acc[nt][3]);
            }
        }
        __syncthreads();
        if (tid == 0) red_release(&g_flag[bid * FSTRIDE]);
    }

    if (wid < 4) {
        const unsigned* a = &g_flag[(wid * 32 + lane) * FSTRIDE];
        int spins = 0;
        bool done = false;
        while (true) {
            if (!done) done = (ld_relaxed(a) >= (unsigned)T_STEPS);
            if (__ballot_sync(0xffffffffu, !done) == 0) break;
            if (++spins > 8192) __nanosleep(64);
        }
        asm volatile("fence.acq_rel.gpu;" ::: "memory");
    }
    __syncthreads();
    if (owned) {
        *reinterpret_cast<float4*>(&out[(size_t)(T_STEPS - 1) * BH + my_off]) = saved;
        *reinterpret_cast<float4*>(&out[(size_t)T_STEPS * BH + my_off]) = saved;
    }

    __syncthreads();
    if (tid == 0) {
        unsigned d = atomicAdd(&g_done, 1u);
        if (d == (unsigned)(gridDim.x - 1)) {
            for (int i = 0; i < SC_BLOCKS; i++) g_flag[i * FSTRIDE] = 0;
            g_done = 0;
            __threadfence();
        }
    }
}

// ============================================================
extern "C" void kernel_launch(void* const* d_in, const int* in_sizes, int n_in,
                              void* d_out, int out_size) {
    const float* X    = (const float*)d_in[0];
    const float* W_xh = (const float*)d_in[1];
    const float* W_hh = (const float*)d_in[2];
    const float* b_h  = (const float*)d_in[3];
    float* out = (float*)d_out;

    {
        dim3 grid(HID / 128, (T_STEPS * BATCH) / 128);
        xp_gemm_tf32<<<grid, 256>>>(X, W_xh, b_h, out);
    }
    rnn_scan<<<SC_BLOCKS, 512>>>(W_hh, out);
}